// round 12
// baseline (speedup 1.0000x reference)
#include <cuda_runtime.h>
#include <cstdint>

#define B 8192
#define TC 128                 // tile cols (warp = 32 lanes x float4)
#define TR 256                 // tile rows
#define GX (B / TC)            // 64 col stripes
#define GY (B / TR)            // 32 row bands

#define NEG_INF __int_as_float(0xff800000)
#define ENC_OFF 0x007FFFFFu    // shifted so enc2(-inf) == 0 (zero-init scratch)

// Final max arrays (zero-init == enc(-inf); K2 resets them after reading).
__device__ unsigned g_rowmax[B];         // 32 KB
__device__ unsigned g_colmax[B];         // 32 KB
__device__ float    g_diag[B];

// Monotone float<->uint encoding (shifted): atomicMax(unsigned) == float max.
__device__ __forceinline__ unsigned enc2(float f) {
    unsigned u = __float_as_uint(f);
    return (u ^ ((unsigned)((int)u >> 31) | 0x80000000u)) - ENC_OFF;
}
__device__ __forceinline__ float dec2(unsigned e) {
    unsigned x = e + ENC_OFF;
    unsigned u = (x & 0x80000000u) ? (x ^ 0x80000000u) : ~x;
    return __uint_as_float(u);
}

// Warp-wide max via integer REDUX (legal on sm_103a; f32 variant is not).
// Operates on the monotone encoding, which we want anyway for atomicMax.
__device__ __forceinline__ unsigned warp_max_enc(unsigned v) {
    unsigned r;
    asm("redux.sync.max.u32 %0, %1, 0xffffffff;" : "=r"(r) : "r"(v));
    return r;
}

// ---------------------------------------------------------------------------
// K1: R10's winning scan; the 5-SHFL row-reduce chain replaced by one
// encode + one REDUX.U32. Encoded row maxes staged in shared; drain-phase
// atomics consume them directly (no decode/re-encode).
// ---------------------------------------------------------------------------
template<bool DIAG>
__device__ __forceinline__ void scan_body(const float* __restrict__ sim,
                                          int rowBase, int colBase,
                                          int tx, int ty, float* cm,
                                          unsigned* s_row) {
    const int gcol0 = colBase + tx * 4;
    #pragma unroll 4
    for (int r = ty; r < TR; r += 8) {
        const int grow = rowBase + r;
        const float4 v = *reinterpret_cast<const float4*>(
            sim + (size_t)grow * B + gcol0);

        float e0 = v.x, e1 = v.y, e2 = v.z, e3 = v.w;
        if (DIAG) {
            if (grow == gcol0 + 0) { g_diag[grow] = e0; e0 = NEG_INF; }
            if (grow == gcol0 + 1) { g_diag[grow] = e1; e1 = NEG_INF; }
            if (grow == gcol0 + 2) { g_diag[grow] = e2; e2 = NEG_INF; }
            if (grow == gcol0 + 3) { g_diag[grow] = e3; e3 = NEG_INF; }
        }

        cm[0] = fmaxf(cm[0], e0);
        cm[1] = fmaxf(cm[1], e1);
        cm[2] = fmaxf(cm[2], e2);
        cm[3] = fmaxf(cm[3], e3);

        const unsigned rmax_enc =
            warp_max_enc(enc2(fmaxf(fmaxf(e0, e1), fmaxf(e2, e3))));
        if (tx == 0)
            s_row[r] = rmax_enc;           // STS (encoded), not STG
    }
}

__global__ void __launch_bounds__(256) wtl_k1(const float* __restrict__ sim) {
    const int tx = threadIdx.x;            // 0..31
    const int ty = threadIdx.y;            // 0..7
    const int tid = ty * 32 + tx;
    const int colBase = blockIdx.x * TC;
    const int rowBase = blockIdx.y * TR;

    __shared__ unsigned s_row[TR];         // 1 KB (encoded)
    __shared__ float    s_col[8][TC];      // 4 KB

    float cm[4];
    cm[0] = cm[1] = cm[2] = cm[3] = NEG_INF;

    // Diagonal intersects this tile iff bx/2 == by (TC=128, TR=256).
    if ((blockIdx.x >> 1) == blockIdx.y)
        scan_body<true >(sim, rowBase, colBase, tx, ty, cm, s_row);
    else
        scan_body<false>(sim, rowBase, colBase, tx, ty, cm, s_row);

    *reinterpret_cast<float4*>(&s_col[ty][tx * 4]) =
        make_float4(cm[0], cm[1], cm[2], cm[3]);
    __syncthreads();

    // Drain-phase atomics: 256 row + 128 col atomicMax per block.
    atomicMax(&g_rowmax[rowBase + tid], s_row[tid]);   // already encoded

    if (tid < TC) {
        float m = s_col[0][tid];
        #pragma unroll
        for (int s = 1; s < 8; s++) m = fmaxf(m, s_col[s][tid]);
        atomicMax(&g_colmax[colBase + tid], enc2(m));
    }
}

// ---------------------------------------------------------------------------
// K2: ONE block, 1024 threads, 8 indices each. No inter-block protocol.
// Computes losses, resets scratch for replay, fixed-tree reduce.
// ---------------------------------------------------------------------------
__global__ void __launch_bounds__(1024) wtl_k2(float* __restrict__ out) {
    const int tid = threadIdx.x;

    float local = 0.0f;
    #pragma unroll
    for (int k = 0; k < 8; k++) {
        const int i = k * 1024 + tid;      // coalesced
        const float rm  = dec2(g_rowmax[i]);
        const float cx  = dec2(g_colmax[i]);
        const float pos = g_diag[i];

        g_rowmax[i] = 0u;                  // reset for next graph replay
        g_colmax[i] = 0u;

        const float pos_loss = fmaxf(0.2f * pos * pos - 0.7f * pos + 0.5f, 0.0f);
        if (rm + 1.0f > pos)
            local += pos_loss + fmaxf(0.9f * rm * rm - 0.4f * rm + 0.03f, 0.0f);
        if (cx + 1.0f > pos)
            local += pos_loss + fmaxf(0.9f * cx * cx - 0.4f * cx + 0.03f, 0.0f);
    }

    // deterministic fixed-tree reduction over 1024 threads
    __shared__ float s_sum[1024];
    s_sum[tid] = local;
    __syncthreads();
    #pragma unroll
    for (int s = 512; s > 0; s >>= 1) {
        if (tid < s) s_sum[tid] += s_sum[tid + s];
        __syncthreads();
    }
    if (tid == 0) out[0] = s_sum[0] / (float)B;
}

extern "C" void kernel_launch(void* const* d_in, const int* in_sizes, int n_in,
                              void* d_out, int out_size) {
    const float* sim = (const float*)d_in[0];
    float* out = (float*)d_out;

    dim3 grid1(GX, GY);        // (64, 32)
    dim3 block1(32, 8);
    wtl_k1<<<grid1, block1>>>(sim);
    wtl_k2<<<1, 1024>>>(out);
}